// round 17
// baseline (speedup 1.0000x reference)
#include <cuda_runtime.h>
#include <cstdint>

#define DEPTH    3
#define MARGIN   0.1f
#define BETA     0.5f
#define MAXN     16384          // max tokens (B*T); actual 2048
#define MAXWIDTH 262144         // max 2*V; actual 64000
#define TPB      128
#define HTPB     256
#define FTPB     256
#define FPSCALE  1073741824.0   // 2^30 fixed-point scale

// ---- device scratch (allocation-free; zero-initialized at module load;
//      g_hist/accumulators restored to zero by final_kernel every call) ----
// Count-min sketch is algebraically degenerate: salts are a common shift per
// depth, so min over depths == multiplicity of (combined % width).
__device__ int       g_hist[MAXWIDTH];
__device__ int       g_cm  [MAXN];       // bucket per token
__device__ long long g_acc_nll;          // fixed-point 2^30 accumulators
__device__ long long g_acc_mask;         // (integer adds: order-independent,
__device__ long long g_acc_basis;        //  hence bit-deterministic)

// fast softplus for the bulk sum (MUFU EX2/LG2 path)
__device__ __forceinline__ float softplus_fast(float x) {
    float e = __expf(-fabsf(x));
    return fmaxf(x, 0.0f) + __logf(1.0f + e);
}
// precise softplus for the two per-row scalars feeding log()
__device__ __forceinline__ float softplus_precise(float x) {
    float e = expf(-fabsf(x));
    return fmaxf(x, 0.0f) + log1pf(e);
}
// fast tanh for x >= 0: 1 - 2/(e^{2x}+1)
__device__ __forceinline__ float tanh_pos(float x) {
    return 1.0f - 2.0f * __frcp_rn(__expf(2.0f * x) + 1.0f);
}

// PDL controls
__device__ __forceinline__ void pdl_trigger() {
#if __CUDA_ARCH__ >= 900
    asm volatile("griddepcontrol.launch_dependents;");
#endif
}
__device__ __forceinline__ void pdl_wait() {
#if __CUDA_ARCH__ >= 900
    asm volatile("griddepcontrol.wait;");
#endif
}

__device__ __forceinline__ void red_add_s64(long long* p, long long v) {
    atomicAdd(reinterpret_cast<unsigned long long*>(p),
              static_cast<unsigned long long>(v));   // return unused -> RED
}

// ---------------- kernel 1: hash + histogram (tiny, runs first) ----------
// Triggers PDL at entry so row_kernel launches immediately; its own work
// (~2us) fully overlaps row_kernel's stream startup.
__global__ void __launch_bounds__(HTPB) hash_kernel(const long long* __restrict__ inputs,
                                                    const long long* __restrict__ targets,
                                                    int N, int V) {
    pdl_trigger();
    int n = blockIdx.x * HTPB + threadIdx.x;
    if (n < N) {
        long long width = 2LL * V;
        long long combined = inputs[n] * 31337LL + targets[n] * 2654435769LL;
        long long c = combined % width;
        if (c < 0) c += width;
        g_cm[n] = (int)c;
        atomicAdd(&g_hist[(int)c], 1);
    }
}

// ---------------- kernel 2: stream + complete per-row epilogue -----------
// One block per row; the only pass over the big tensor. Thread 0 waits on
// the (long-finished) hash grid, queries the histogram, and accumulates all
// three loss terms via fire-and-forget integer REDs (deterministic).
__global__ void __launch_bounds__(TPB) row_kernel(const float* __restrict__ logits,
                                                  const long long* __restrict__ targets,
                                                  int V, int vec_ok, int N) {
    pdl_trigger();   // let final_kernel launch early

    const int r   = blockIdx.x;
    const int tid = threadIdx.x;
    const float* row = logits + (size_t)r * V;

    float acc = 0.0f;
    if (vec_ok) {
        const float4* row4 = reinterpret_cast<const float4*>(row);
        const int n4 = V >> 2;
#pragma unroll 4
        for (int i = tid; i < n4; i += TPB) {
            float4 v = __ldcs(&row4[i]);   // single-use stream: evict-first
            acc += softplus_fast(v.x);
            acc += softplus_fast(v.y);
            acc += softplus_fast(v.z);
            acc += softplus_fast(v.w);
        }
    } else {
        for (int i = tid; i < V; i += TPB)
            acc += softplus_fast(row[i]);
    }

    __shared__ float warp_sums[TPB / 32];
#pragma unroll
    for (int off = 16; off > 0; off >>= 1)
        acc += __shfl_xor_sync(0xFFFFFFFFu, acc, off);
    int lane = tid & 31, wid = tid >> 5;
    if (lane == 0) warp_sums[wid] = acc;
    __syncthreads();

    if (tid == 0) {
        float S = 0.0f;
#pragma unroll
        for (int w = 0; w < TPB / 32; w++) S += warp_sums[w];

        long long t = targets[r];
        bool valid  = (t != -1);
        int ti = (t >= 0 && t < V) ? (int)t : 0;
        float spt = softplus_precise(row[ti]);
        float spi = softplus_precise(row[0]);

        float scale = fminf(1.0f / (S + 1e-6f), 1.0f);
        float rem   = fmaxf(1.0f - S * scale, 0.0f);
        float p_t   = spt * scale + ((t == 0) ? rem : 0.0f);
        float p_i   = spi * scale + rem;

        float nll  = valid ? logf(fmaxf(p_t, 1e-10f)) : 0.0f;
        float rerr = fmaxf(p_i - p_t + MARGIN, 0.0f);

        // histogram query (hash grid finished ~40us ago; wait is a no-op)
        pdl_wait();
        int c = __ldcg(&g_hist[__ldcg(&g_cm[r])]);
        float basis = rerr * tanh_pos((float)c * 0.1f);

        // deterministic fixed-point accumulation (fire-and-forget REDs)
        red_add_s64(&g_acc_nll,   llrint((double)nll   * FPSCALE));
        red_add_s64(&g_acc_mask,  valid ? (long long)FPSCALE : 0LL);
        red_add_s64(&g_acc_basis, llrint((double)basis * FPSCALE));
    }
}

// ---------------- kernel 3: O(1) finish + state restore (PDL) ------------
__global__ void __launch_bounds__(FTPB) final_kernel(float* __restrict__ out, int N) {
    pdl_wait();   // row grid complete => all REDs at L2
    const int tid = threadIdx.x;

    if (tid == 0) {
        double a = (double)g_acc_nll   / FPSCALE;
        double b = (double)g_acc_mask  / FPSCALE;
        double c = (double)g_acc_basis / FPSCALE;
        out[0] = (float)(-a / fmax(b, 1.0) + (double)BETA * (c / (double)N));
        g_acc_nll = 0; g_acc_mask = 0; g_acc_basis = 0;
    }
    // restore histogram to zero (duplicate buckets all write 0)
    for (int n = tid; n < N; n += FTPB)
        g_hist[__ldcg(&g_cm[n])] = 0;
}

extern "C" void kernel_launch(void* const* d_in, const int* in_sizes, int n_in,
                              void* d_out, int out_size) {
    // Resolve pointers by element count (robust to metadata ordering):
    //   salts: size == DEPTH (unused — algebraically eliminated);
    //   logits: largest; targets then inputs (relative order).
    const float*     logits  = nullptr;
    const long long* tok[2]  = {nullptr, nullptr};
    int ntok_arrays = 0;
    long long logits_size = 0;
    int N = 0;

    for (int i = 0; i < n_in; i++) {
        long long sz = in_sizes[i];
        if (sz == DEPTH) {
            // salts — common per-depth shift cancels in the min
        } else if (sz > 1000000) {
            logits = (const float*)d_in[i];
            logits_size = sz;
        } else {
            if (ntok_arrays < 2) tok[ntok_arrays] = (const long long*)d_in[i];
            ntok_arrays++;
            N = (int)sz;
        }
    }
    const long long* targets = tok[0];
    const long long* inputs  = tok[1];

    int V = (N > 0) ? (int)(logits_size / N) : 0;
    float* out = (float*)d_out;

    int vec_ok = (((uintptr_t)logits & 15) == 0) && (V % 4 == 0);

    // PDL chain: hash -> row -> final. Each predecessor triggers at entry,
    // so successors launch immediately and only their data-dependent parts
    // wait (via griddepcontrol.wait).
    cudaLaunchAttribute attrs[1];
    attrs[0].id = cudaLaunchAttributeProgrammaticStreamSerialization;
    attrs[0].val.programmaticStreamSerializationAllowed = 1;

    hash_kernel<<<(N + HTPB - 1) / HTPB, HTPB>>>(inputs, targets, N, V);

    cudaLaunchConfig_t cfg_row = {};
    cfg_row.gridDim  = dim3(N, 1, 1);
    cfg_row.blockDim = dim3(TPB, 1, 1);
    cfg_row.stream = 0;
    cfg_row.attrs = attrs;
    cfg_row.numAttrs = 1;
    cudaLaunchKernelEx(&cfg_row, row_kernel, logits, targets, V, vec_ok, N);

    cudaLaunchConfig_t cfg_fin = {};
    cfg_fin.gridDim  = dim3(1, 1, 1);
    cfg_fin.blockDim = dim3(FTPB, 1, 1);
    cfg_fin.stream = 0;
    cfg_fin.attrs = attrs;
    cfg_fin.numAttrs = 1;
    cudaLaunchKernelEx(&cfg_fin, final_kernel, out, N);
}